// round 13
// baseline (speedup 1.0000x reference)
#include <cuda_runtime.h>
#include <cuda_bf16.h>

#define N_NODES   80000
#define NODES_PB  10000
#define NBATCH    8
#define NEDGES    2560000
#define IN_DIM    128
#define H1        32
#define H2        64

#define SCAN_B    1024
#define NBLK_SCAN ((N_NODES + SCAN_B - 1) / SCAN_B)   // 79

// ---- scratch (__device__ globals; no allocation allowed) ----
__device__ float g_dinv[N_NODES];
__device__ int   g_cnt[N_NODES];
__device__ int   g_rowstart[N_NODES + 1];
__device__ int   g_cursor[N_NODES];
__device__ int   g_bsum[NBLK_SCAN];
__device__ int   g_esrc[NEDGES];                      // src only (features pre-scaled)

__device__ __align__(128) float g_h1t[N_NODES * H1];  // dinv * (x@W1)
__device__ __align__(128) float g_h1o[N_NODES * H1];  // dinv * relu(agg1+b1)
__device__ __align__(128) float g_h2o[N_NODES * H2];  // relu(agg2@W2+b2)

// ---------------------------------------------------------------------------
// CSR build
// ---------------------------------------------------------------------------
__global__ void k_cnt_init() {
    int i = blockIdx.x * blockDim.x + threadIdx.x;
    if (i < N_NODES) g_cnt[i] = 0;
}

__global__ void k_deg_count(const int* __restrict__ ei) {
    int e = blockIdx.x * blockDim.x + threadIdx.x;
    if (e < NEDGES) atomicAdd(&g_cnt[ei[NEDGES + e]], 1);
}

__global__ void k_scan_a() {
    __shared__ int sh[SCAN_B / 32];
    int i = blockIdx.x * SCAN_B + threadIdx.x;
    int v = (i < N_NODES) ? g_cnt[i] : 0;
    #pragma unroll
    for (int o = 16; o > 0; o >>= 1) v += __shfl_down_sync(0xFFFFFFFFu, v, o);
    if ((threadIdx.x & 31) == 0) sh[threadIdx.x >> 5] = v;
    __syncthreads();
    if (threadIdx.x < SCAN_B / 32) {
        int t = sh[threadIdx.x];
        #pragma unroll
        for (int o = SCAN_B / 64; o > 0; o >>= 1) t += __shfl_down_sync(0xFFFFFFFFu, t, o);
        if (threadIdx.x == 0) g_bsum[blockIdx.x] = t;
    }
    if (blockIdx.x == 0 && threadIdx.x == 0) g_rowstart[N_NODES] = NEDGES;
}

__global__ void k_scan_c() {
    __shared__ int sh[SCAN_B];
    __shared__ int s_off;
    int tid = threadIdx.x;

    if (tid < 32) {
        int v = 0;
        for (int b = tid; b < blockIdx.x; b += 32) v += g_bsum[b];
        #pragma unroll
        for (int o = 16; o > 0; o >>= 1) v += __shfl_down_sync(0xFFFFFFFFu, v, o);
        if (tid == 0) s_off = v;
    }

    int i = blockIdx.x * SCAN_B + tid;
    int v = (i < N_NODES) ? g_cnt[i] : 0;
    sh[tid] = v;
    __syncthreads();
    #pragma unroll
    for (int off = 1; off < SCAN_B; off <<= 1) {
        int t = (tid >= off) ? sh[tid - off] : 0;
        __syncthreads();
        sh[tid] += t;
        __syncthreads();
    }
    if (i < N_NODES) {
        int excl = sh[tid] - v + s_off;
        g_rowstart[i] = excl;
        g_cursor[i]   = excl;
        g_dinv[i]     = rsqrtf((float)(v + 1));   // +1 self-loop
    }
}

__global__ void k_place(const int* __restrict__ ei) {
    int e = blockIdx.x * blockDim.x + threadIdx.x;
    if (e >= NEDGES) return;
    int s = ei[e];
    int d = ei[NEDGES + e];
    int slot = atomicAdd(&g_cursor[d], 1);
    g_esrc[slot] = s;
}

// ---------------------------------------------------------------------------
// GEMM1: g_h1t = dinv * (x @ W1)   (80000x128 @ 128x32), scaled epilogue
// ---------------------------------------------------------------------------
__global__ void k_gemm1(const float* __restrict__ x, const float* __restrict__ W1) {
    __shared__ float Ws[IN_DIM][H1];          // [k][col] 16KB
    __shared__ float xsT[32][132];            // [k][row] transposed, padded
    int row0 = blockIdx.x * 128;
    int tx = threadIdx.x & 7;                 // cols tx*4 .. +3
    int ty = threadIdx.x >> 3;                // rows ty*4 .. +3

    for (int i = threadIdx.x; i < IN_DIM * H1; i += 256)
        Ws[i >> 5][i & 31] = W1[i];

    float acc[4][4] = {};
    for (int k0 = 0; k0 < IN_DIM; k0 += 32) {
        __syncthreads();
        for (int i = threadIdx.x; i < 128 * 32; i += 256) {
            int r = i >> 5, k = i & 31;
            xsT[k][r] = x[(size_t)(row0 + r) * IN_DIM + k0 + k];
        }
        __syncthreads();
        #pragma unroll
        for (int k = 0; k < 32; k++) {
            float4 xv = *(const float4*)&xsT[k][ty * 4];
            float4 wv = *(const float4*)&Ws[k0 + k][tx * 4];
            acc[0][0] += xv.x * wv.x; acc[0][1] += xv.x * wv.y; acc[0][2] += xv.x * wv.z; acc[0][3] += xv.x * wv.w;
            acc[1][0] += xv.y * wv.x; acc[1][1] += xv.y * wv.y; acc[1][2] += xv.y * wv.z; acc[1][3] += xv.y * wv.w;
            acc[2][0] += xv.z * wv.x; acc[2][1] += xv.z * wv.y; acc[2][2] += xv.z * wv.z; acc[2][3] += xv.z * wv.w;
            acc[3][0] += xv.w * wv.x; acc[3][1] += xv.w * wv.y; acc[3][2] += xv.w * wv.z; acc[3][3] += xv.w * wv.w;
        }
    }
    #pragma unroll
    for (int i = 0; i < 4; i++) {
        int r = row0 + ty * 4 + i;
        float dn = g_dinv[r];
        float4 o = make_float4(acc[i][0] * dn, acc[i][1] * dn, acc[i][2] * dn, acc[i][3] * dn);
        *(float4*)&g_h1t[(size_t)r * H1 + tx * 4] = o;
    }
}

// ---------------------------------------------------------------------------
// gather core: warp per node, 4 edges in flight (8 lanes x float4 each),
// weight-free sum of pre-scaled rows incl. self row. Full xor-reduction so
// ALL lanes hold the complete 32-col sum (replicated per cl group).
// ---------------------------------------------------------------------------
__device__ __forceinline__ float4 gather_rows(const float4* __restrict__ h4,
                                              int node, int lane) {
    int cg = lane >> 3;        // edge subgroup 0..3
    int cl = lane & 7;         // float4 column group 0..7
    int beg = g_rowstart[node], end = g_rowstart[node + 1];

    float4 acc = make_float4(0.f, 0.f, 0.f, 0.f);
    if (cg == 0) acc = h4[(size_t)node * 8 + cl];    // self (pre-scaled)

    int e = beg + cg;
    if (e < end) {
        int s = g_esrc[e];
        while (true) {
            int en = e + 4;
            bool more = en < end;
            int sn = more ? g_esrc[en] : 0;
            float4 v = h4[(size_t)s * 8 + cl];
            acc.x += v.x; acc.y += v.y; acc.z += v.z; acc.w += v.w;
            if (!more) break;
            s = sn; e = en;
        }
    }

    __syncwarp();
    #pragma unroll
    for (int o = 8; o <= 16; o <<= 1) {
        acc.x += __shfl_xor_sync(0xFFFFFFFFu, acc.x, o);
        acc.y += __shfl_xor_sync(0xFFFFFFFFu, acc.y, o);
        acc.z += __shfl_xor_sync(0xFFFFFFFFu, acc.z, o);
        acc.w += __shfl_xor_sync(0xFFFFFFFFu, acc.w, o);
    }
    return acc;
}

// gather1: h1o_scaled = dinv * relu(dinv * gather(h1t_scaled) + b1)
__global__ void k_gather1(const float* __restrict__ b1) {
    int node = (blockIdx.x * blockDim.x + threadIdx.x) >> 5;
    if (node >= N_NODES) return;
    int lane = threadIdx.x & 31;
    float4 acc = gather_rows((const float4*)g_h1t, node, lane);
    if ((lane >> 3) == 0) {
        int cl = lane & 7;
        float dn = g_dinv[node];
        float4 bv = *(const float4*)&b1[cl * 4];
        float4 o;
        o.x = dn * fmaxf(dn * acc.x + bv.x, 0.f);
        o.y = dn * fmaxf(dn * acc.y + bv.y, 0.f);
        o.z = dn * fmaxf(dn * acc.z + bv.z, 0.f);
        o.w = dn * fmaxf(dn * acc.w + bv.w, 0.f);
        *(float4*)&g_h1o[(size_t)node * H1 + cl * 4] = o;
    }
}

// ---------------------------------------------------------------------------
// fused gather2 + GEMM2: a2 = dinv * gather(h1o_scaled);
//   h2o = relu(a2 @ W2 + b2)  computed in-warp via shfl broadcast.
// 1024 threads = 32 nodes/block to amortize the W2 smem load.
// ---------------------------------------------------------------------------
__global__ void k_gather2_gemm2(const float* __restrict__ W2, const float* __restrict__ b2) {
    __shared__ float W2s[H1][H2];    // 8KB
    __shared__ float b2s[H2];
    for (int i = threadIdx.x; i < H1 * H2; i += 1024) W2s[i >> 6][i & 63] = W2[i];
    if (threadIdx.x < H2) b2s[threadIdx.x] = b2[threadIdx.x];
    __syncthreads();

    int node = (blockIdx.x * blockDim.x + threadIdx.x) >> 5;
    if (node >= N_NODES) return;
    int lane = threadIdx.x & 31;

    float4 acc = gather_rows((const float4*)g_h1o, node, lane);
    float dn = g_dinv[node];
    acc.x *= dn; acc.y *= dn; acc.z *= dn; acc.w *= dn;

    // every lane now holds a2[cl*4 .. cl*4+3]; broadcast each k and mat-vec
    float o0 = 0.f, o1 = 0.f;
    #pragma unroll
    for (int k = 0; k < H1; k++) {
        float comp = ((k & 3) == 0) ? acc.x : ((k & 3) == 1) ? acc.y : ((k & 3) == 2) ? acc.z : acc.w;
        float a2k = __shfl_sync(0xFFFFFFFFu, comp, k >> 2);
        o0 += a2k * W2s[k][lane];
        o1 += a2k * W2s[k][lane + 32];
    }
    size_t base = (size_t)node * H2;
    g_h2o[base + lane]      = fmaxf(o0 + b2s[lane],      0.f);
    g_h2o[base + lane + 32] = fmaxf(o1 + b2s[lane + 32], 0.f);
}

// ---------------------------------------------------------------------------
// readout
// ---------------------------------------------------------------------------
__global__ void k_out_init(float* __restrict__ out, const float* __restrict__ bout) {
    int b = threadIdx.x;
    if (b < NBATCH) out[b] = bout[0];
}

__global__ void k_out_reduce(const float* __restrict__ Wout, float* __restrict__ out) {
    const int LEN = NODES_PB * H2;   // 640000
    int b = blockIdx.y;
    const float4* h = (const float4*)(g_h2o + (size_t)b * LEN);
    const float4* w = (const float4*)Wout;
    float s = 0.f;
    for (int j = blockIdx.x * blockDim.x + threadIdx.x; j < LEN / 4; j += gridDim.x * blockDim.x) {
        float4 hv = h[j], wv = w[j];
        s += hv.x * wv.x + hv.y * wv.y + hv.z * wv.z + hv.w * wv.w;
    }
    #pragma unroll
    for (int o = 16; o > 0; o >>= 1) s += __shfl_down_sync(0xFFFFFFFFu, s, o);
    __shared__ float ws[8];
    if ((threadIdx.x & 31) == 0) ws[threadIdx.x >> 5] = s;
    __syncthreads();
    if (threadIdx.x < 8) {
        float t = ws[threadIdx.x];
        #pragma unroll
        for (int o = 4; o > 0; o >>= 1) t += __shfl_down_sync(0xFFu, t, o);
        if (threadIdx.x == 0) atomicAdd(&out[b], t);
    }
}

// ---------------------------------------------------------------------------
extern "C" void kernel_launch(void* const* d_in, const int* in_sizes, int n_in,
                              void* d_out, int out_size) {
    const float* x    = (const float*)d_in[0];
    const int*   ei   = (const int*)d_in[1];     // int32 (JAX demotes int64)
    const float* W1   = (const float*)d_in[2];
    const float* b1   = (const float*)d_in[3];
    const float* W2   = (const float*)d_in[4];
    const float* b2   = (const float*)d_in[5];
    const float* Wout = (const float*)d_in[6];
    const float* bout = (const float*)d_in[7];
    float*       out  = (float*)d_out;

    const int T = 256;
    const int nodeBlk = (N_NODES + T - 1) / T;
    const int edgeBlk = (NEDGES + T - 1) / T;
    const int warpBlk = (N_NODES * 32 + T - 1) / T;

    // CSR build
    k_cnt_init<<<nodeBlk, T>>>();
    k_deg_count<<<edgeBlk, T>>>(ei);
    k_scan_a<<<NBLK_SCAN, SCAN_B>>>();
    k_scan_c<<<NBLK_SCAN, SCAN_B>>>();
    k_place<<<edgeBlk, T>>>(ei);

    // layer 1
    k_gemm1<<<N_NODES / 128, T>>>(x, W1);
    k_gather1<<<warpBlk, T>>>(b1);

    // layer 2 (fused gather + transform)
    k_gather2_gemm2<<<(N_NODES * 32 + 1023) / 1024, 1024>>>(W2, b2);

    // readout
    k_out_init<<<1, 32>>>(out, bout);
    dim3 og(40, NBATCH);
    k_out_reduce<<<og, T>>>(Wout, out);
}

// round 16
// speedup vs baseline: 1.4355x; 1.4355x over previous
#include <cuda_runtime.h>
#include <cuda_bf16.h>

#define N_NODES   80000
#define NODES_PB  10000
#define NBATCH    8
#define NEDGES    2560000
#define IN_DIM    128
#define H1        32
#define H2        64

#define SCAN_B    1024
#define NBLK_SCAN ((N_NODES + SCAN_B - 1) / SCAN_B)   // 79

// ---- scratch (__device__ globals; no allocation allowed) ----
__device__ float g_dinv[N_NODES];
__device__ int   g_cnt[N_NODES];
__device__ int   g_rowstart[N_NODES + 1];
__device__ int   g_cursor[N_NODES];
__device__ int   g_bsum[NBLK_SCAN];
__device__ int   g_esrc[NEDGES];                      // src only (features pre-scaled)

__device__ __align__(128) float g_h1t[N_NODES * H1];  // dinv * (x@W1)
__device__ __align__(128) float g_h1o[N_NODES * H1];  // dinv * relu(agg1+b1)
__device__ __align__(128) float g_a2 [N_NODES * H1];  // dinv * gather(h1o)
__device__ __align__(128) float g_h2o[N_NODES * H2];  // relu(a2@W2+b2)

// ---------------------------------------------------------------------------
// CSR build
// ---------------------------------------------------------------------------
__global__ void k_cnt_init() {
    int i = blockIdx.x * blockDim.x + threadIdx.x;
    if (i < N_NODES) g_cnt[i] = 0;
}

__global__ void k_deg_count(const int* __restrict__ ei) {
    int e = blockIdx.x * blockDim.x + threadIdx.x;
    if (e < NEDGES) atomicAdd(&g_cnt[ei[NEDGES + e]], 1);
}

__global__ void k_scan_a() {
    __shared__ int sh[SCAN_B / 32];
    int i = blockIdx.x * SCAN_B + threadIdx.x;
    int v = (i < N_NODES) ? g_cnt[i] : 0;
    #pragma unroll
    for (int o = 16; o > 0; o >>= 1) v += __shfl_down_sync(0xFFFFFFFFu, v, o);
    if ((threadIdx.x & 31) == 0) sh[threadIdx.x >> 5] = v;
    __syncthreads();
    if (threadIdx.x < SCAN_B / 32) {
        int t = sh[threadIdx.x];
        #pragma unroll
        for (int o = SCAN_B / 64; o > 0; o >>= 1) t += __shfl_down_sync(0xFFFFFFFFu, t, o);
        if (threadIdx.x == 0) g_bsum[blockIdx.x] = t;
    }
    if (blockIdx.x == 0 && threadIdx.x == 0) g_rowstart[N_NODES] = NEDGES;
}

__global__ void k_scan_c() {
    __shared__ int sh[SCAN_B];
    __shared__ int s_off;
    int tid = threadIdx.x;

    if (tid < 32) {
        int v = 0;
        for (int b = tid; b < blockIdx.x; b += 32) v += g_bsum[b];
        #pragma unroll
        for (int o = 16; o > 0; o >>= 1) v += __shfl_down_sync(0xFFFFFFFFu, v, o);
        if (tid == 0) s_off = v;
    }

    int i = blockIdx.x * SCAN_B + tid;
    int v = (i < N_NODES) ? g_cnt[i] : 0;
    sh[tid] = v;
    __syncthreads();
    #pragma unroll
    for (int off = 1; off < SCAN_B; off <<= 1) {
        int t = (tid >= off) ? sh[tid - off] : 0;
        __syncthreads();
        sh[tid] += t;
        __syncthreads();
    }
    if (i < N_NODES) {
        int excl = sh[tid] - v + s_off;
        g_rowstart[i] = excl;
        g_cursor[i]   = excl;
        g_dinv[i]     = rsqrtf((float)(v + 1));   // +1 self-loop
    }
}

__global__ void k_place(const int* __restrict__ ei) {
    int e = blockIdx.x * blockDim.x + threadIdx.x;
    if (e >= NEDGES) return;
    int s = ei[e];
    int d = ei[NEDGES + e];
    int slot = atomicAdd(&g_cursor[d], 1);
    g_esrc[slot] = s;
}

// ---------------------------------------------------------------------------
// GEMM1: g_h1t = dinv * (x @ W1)   (80000x128 @ 128x32), scaled epilogue
// ---------------------------------------------------------------------------
__global__ void k_gemm1(const float* __restrict__ x, const float* __restrict__ W1) {
    __shared__ float Ws[IN_DIM][H1];          // [k][col] 16KB
    __shared__ float xsT[32][132];            // [k][row] transposed, padded
    int row0 = blockIdx.x * 128;
    int tx = threadIdx.x & 7;                 // cols tx*4 .. +3
    int ty = threadIdx.x >> 3;                // rows ty*4 .. +3

    for (int i = threadIdx.x; i < IN_DIM * H1; i += 256)
        Ws[i >> 5][i & 31] = W1[i];

    float acc[4][4] = {};
    for (int k0 = 0; k0 < IN_DIM; k0 += 32) {
        __syncthreads();
        for (int i = threadIdx.x; i < 128 * 32; i += 256) {
            int r = i >> 5, k = i & 31;
            xsT[k][r] = x[(size_t)(row0 + r) * IN_DIM + k0 + k];
        }
        __syncthreads();
        #pragma unroll
        for (int k = 0; k < 32; k++) {
            float4 xv = *(const float4*)&xsT[k][ty * 4];
            float4 wv = *(const float4*)&Ws[k0 + k][tx * 4];
            acc[0][0] += xv.x * wv.x; acc[0][1] += xv.x * wv.y; acc[0][2] += xv.x * wv.z; acc[0][3] += xv.x * wv.w;
            acc[1][0] += xv.y * wv.x; acc[1][1] += xv.y * wv.y; acc[1][2] += xv.y * wv.z; acc[1][3] += xv.y * wv.w;
            acc[2][0] += xv.z * wv.x; acc[2][1] += xv.z * wv.y; acc[2][2] += xv.z * wv.z; acc[2][3] += xv.z * wv.w;
            acc[3][0] += xv.w * wv.x; acc[3][1] += xv.w * wv.y; acc[3][2] += xv.w * wv.z; acc[3][3] += xv.w * wv.w;
        }
    }
    #pragma unroll
    for (int i = 0; i < 4; i++) {
        int r = row0 + ty * 4 + i;
        float dn = g_dinv[r];
        float4 o = make_float4(acc[i][0] * dn, acc[i][1] * dn, acc[i][2] * dn, acc[i][3] * dn);
        *(float4*)&g_h1t[(size_t)r * H1 + tx * 4] = o;
    }
}

// ---------------------------------------------------------------------------
// gather core: warp per node, 4 edges in flight (8 lanes x float4 each),
// weight-free sum of pre-scaled rows incl. self row, xor-reduced to cg==0.
// ---------------------------------------------------------------------------
__device__ __forceinline__ float4 gather_rows(const float4* __restrict__ h4,
                                              int node, int lane) {
    int cg = lane >> 3;        // edge subgroup 0..3
    int cl = lane & 7;         // float4 column group 0..7
    int beg = g_rowstart[node], end = g_rowstart[node + 1];

    float4 acc = make_float4(0.f, 0.f, 0.f, 0.f);
    if (cg == 0) acc = h4[(size_t)node * 8 + cl];    // self (pre-scaled)

    int e = beg + cg;
    if (e < end) {
        int s = g_esrc[e];
        while (true) {
            int en = e + 4;
            bool more = en < end;
            int sn = more ? g_esrc[en] : 0;
            float4 v = h4[(size_t)s * 8 + cl];
            acc.x += v.x; acc.y += v.y; acc.z += v.z; acc.w += v.w;
            if (!more) break;
            s = sn; e = en;
        }
    }

    __syncwarp();
    #pragma unroll
    for (int o = 8; o <= 16; o <<= 1) {
        acc.x += __shfl_xor_sync(0xFFFFFFFFu, acc.x, o);
        acc.y += __shfl_xor_sync(0xFFFFFFFFu, acc.y, o);
        acc.z += __shfl_xor_sync(0xFFFFFFFFu, acc.z, o);
        acc.w += __shfl_xor_sync(0xFFFFFFFFu, acc.w, o);
    }
    return acc;
}

// gather1: h1o_scaled = dinv * relu(dinv * gather(h1t_scaled) + b1)
__global__ void k_gather1(const float* __restrict__ b1) {
    int node = (blockIdx.x * blockDim.x + threadIdx.x) >> 5;
    if (node >= N_NODES) return;
    int lane = threadIdx.x & 31;
    float4 acc = gather_rows((const float4*)g_h1t, node, lane);
    if ((lane >> 3) == 0) {
        int cl = lane & 7;
        float dn = g_dinv[node];
        float4 bv = *(const float4*)&b1[cl * 4];
        float4 o;
        o.x = dn * fmaxf(dn * acc.x + bv.x, 0.f);
        o.y = dn * fmaxf(dn * acc.y + bv.y, 0.f);
        o.z = dn * fmaxf(dn * acc.z + bv.z, 0.f);
        o.w = dn * fmaxf(dn * acc.w + bv.w, 0.f);
        *(float4*)&g_h1o[(size_t)node * H1 + cl * 4] = o;
    }
}

// gather2: a2 = dinv * gather(h1o_scaled)    (transform done by k_gemm2)
__global__ void k_gather2() {
    int node = (blockIdx.x * blockDim.x + threadIdx.x) >> 5;
    if (node >= N_NODES) return;
    int lane = threadIdx.x & 31;
    float4 acc = gather_rows((const float4*)g_h1o, node, lane);
    if ((lane >> 3) == 0) {
        int cl = lane & 7;
        float dn = g_dinv[node];
        float4 o = make_float4(acc.x * dn, acc.y * dn, acc.z * dn, acc.w * dn);
        *(float4*)&g_a2[(size_t)node * H1 + cl * 4] = o;
    }
}

// ---------------------------------------------------------------------------
// GEMM2: g_h2o = relu(a2 @ W2 + b2)  (80000x32 @ 32x64)
// 256 thr, tile 128 rows x 64 cols, micro-tile TM=8 x TN=4, K=32.
// ---------------------------------------------------------------------------
__global__ void k_gemm2(const float* __restrict__ W2, const float* __restrict__ b2) {
    __shared__ float Ws2[H1][H2];             // 8KB
    __shared__ float asT[H1][132];            // [k][row] 16.9KB
    int row0 = blockIdx.x * 128;
    int tx = threadIdx.x & 15;                // cols tx*4 .. +3
    int ty = threadIdx.x >> 4;                // rows ty*8 .. +7

    for (int i = threadIdx.x; i < H1 * H2; i += 256)
        Ws2[i >> 6][i & 63] = W2[i];
    for (int i = threadIdx.x; i < 128 * 32; i += 256) {
        int r = i >> 5, k = i & 31;
        asT[k][r] = g_a2[(size_t)(row0 + r) * H1 + k];
    }
    __syncthreads();

    float acc[8][4] = {};
    #pragma unroll
    for (int k = 0; k < H1; k++) {
        float4 x0 = *(const float4*)&asT[k][ty * 8];
        float4 x1 = *(const float4*)&asT[k][ty * 8 + 4];
        float4 wv = *(const float4*)&Ws2[k][tx * 4];
        float xr[8] = {x0.x, x0.y, x0.z, x0.w, x1.x, x1.y, x1.z, x1.w};
        #pragma unroll
        for (int i = 0; i < 8; i++) {
            acc[i][0] += xr[i] * wv.x;
            acc[i][1] += xr[i] * wv.y;
            acc[i][2] += xr[i] * wv.z;
            acc[i][3] += xr[i] * wv.w;
        }
    }
    float4 bv = *(const float4*)&b2[tx * 4];
    #pragma unroll
    for (int i = 0; i < 8; i++) {
        float4 o;
        o.x = fmaxf(acc[i][0] + bv.x, 0.f);
        o.y = fmaxf(acc[i][1] + bv.y, 0.f);
        o.z = fmaxf(acc[i][2] + bv.z, 0.f);
        o.w = fmaxf(acc[i][3] + bv.w, 0.f);
        *(float4*)&g_h2o[(size_t)(row0 + ty * 8 + i) * H2 + tx * 4] = o;
    }
}

// ---------------------------------------------------------------------------
// readout
// ---------------------------------------------------------------------------
__global__ void k_out_init(float* __restrict__ out, const float* __restrict__ bout) {
    int b = threadIdx.x;
    if (b < NBATCH) out[b] = bout[0];
}

__global__ void k_out_reduce(const float* __restrict__ Wout, float* __restrict__ out) {
    const int LEN = NODES_PB * H2;   // 640000
    int b = blockIdx.y;
    const float4* h = (const float4*)(g_h2o + (size_t)b * LEN);
    const float4* w = (const float4*)Wout;
    float s = 0.f;
    for (int j = blockIdx.x * blockDim.x + threadIdx.x; j < LEN / 4; j += gridDim.x * blockDim.x) {
        float4 hv = h[j], wv = w[j];
        s += hv.x * wv.x + hv.y * wv.y + hv.z * wv.z + hv.w * wv.w;
    }
    #pragma unroll
    for (int o = 16; o > 0; o >>= 1) s += __shfl_down_sync(0xFFFFFFFFu, s, o);
    __shared__ float ws[8];
    if ((threadIdx.x & 31) == 0) ws[threadIdx.x >> 5] = s;
    __syncthreads();
    if (threadIdx.x < 8) {
        float t = ws[threadIdx.x];
        #pragma unroll
        for (int o = 4; o > 0; o >>= 1) t += __shfl_down_sync(0xFFu, t, o);
        if (threadIdx.x == 0) atomicAdd(&out[b], t);
    }
}

// ---------------------------------------------------------------------------
extern "C" void kernel_launch(void* const* d_in, const int* in_sizes, int n_in,
                              void* d_out, int out_size) {
    const float* x    = (const float*)d_in[0];
    const int*   ei   = (const int*)d_in[1];     // int32 (JAX demotes int64)
    const float* W1   = (const float*)d_in[2];
    const float* b1   = (const float*)d_in[3];
    const float* W2   = (const float*)d_in[4];
    const float* b2   = (const float*)d_in[5];
    const float* Wout = (const float*)d_in[6];
    const float* bout = (const float*)d_in[7];
    float*       out  = (float*)d_out;

    const int T = 256;
    const int nodeBlk = (N_NODES + T - 1) / T;
    const int edgeBlk = (NEDGES + T - 1) / T;
    const int warpBlk = (N_NODES * 32 + T - 1) / T;

    // CSR build
    k_cnt_init<<<nodeBlk, T>>>();
    k_deg_count<<<edgeBlk, T>>>(ei);
    k_scan_a<<<NBLK_SCAN, SCAN_B>>>();
    k_scan_c<<<NBLK_SCAN, SCAN_B>>>();
    k_place<<<edgeBlk, T>>>(ei);

    // layer 1
    k_gemm1<<<N_NODES / 128, T>>>(x, W1);
    k_gather1<<<warpBlk, T>>>(b1);

    // layer 2
    k_gather2<<<warpBlk, T>>>();
    k_gemm2<<<N_NODES / 128, T>>>(W2, b2);

    // readout
    k_out_init<<<1, 32>>>(out, bout);
    dim3 og(40, NBATCH);
    k_out_reduce<<<og, T>>>(Wout, out);
}